// round 1
// baseline (speedup 1.0000x reference)
#include <cuda_runtime.h>
#include <math.h>

#define T_TOK 2048
#define Dm    512
#define Hm    1024
#define Em    8
#define TILE_T 32
#define CH    128   // H chunk per iteration
#define KT    128   // K tile staged in smem

#define XS 516      // sX row stride (floats), padded vs 512 to dodge bank conflicts
#define WS 132      // weight tile row stride (floats); 33 float4s -> conflict-free column reads
#define HS 128      // sH row stride

// ---- scratch (static device globals; no runtime allocation) ----
__device__ int   g_count[Em];
__device__ int   g_list[Em * T_TOK];       // entry = token*2 + slot
__device__ float g_wt[2 * T_TOK];          // renormalized top-2 weights per (token, slot)
__device__ float g_y[2 * T_TOK * Dm];      // 8 MB: per-(token,slot) unweighted expert output

__global__ void zero_counts_kernel() {
    if (threadIdx.x < Em) g_count[threadIdx.x] = 0;
}

// One warp per token: logits, softmax, top-2, list push.
__global__ void router_kernel(const float* __restrict__ x,
                              const float* __restrict__ wr,
                              const float* __restrict__ br,
                              float* __restrict__ logits_out) {
    int warp = threadIdx.x >> 5;
    int lane = threadIdx.x & 31;
    int t = blockIdx.x * 8 + warp;
    if (t >= T_TOK) return;

    const float4* xv4 = (const float4*)(x) + (size_t)t * (Dm / 4);
    float4 xv[4];
#pragma unroll
    for (int i = 0; i < 4; i++) xv[i] = xv4[i * 32 + lane];

    float lg[Em];
#pragma unroll
    for (int e = 0; e < Em; e++) {
        const float4* wv4 = (const float4*)(wr) + (size_t)e * (Dm / 4);
        float acc = 0.f;
#pragma unroll
        for (int i = 0; i < 4; i++) {
            float4 w = wv4[i * 32 + lane];
            acc += xv[i].x * w.x + xv[i].y * w.y + xv[i].z * w.z + xv[i].w * w.w;
        }
#pragma unroll
        for (int o = 16; o > 0; o >>= 1) acc += __shfl_down_sync(0xffffffffu, acc, o);
        lg[e] = acc;  // valid in lane 0
    }

    if (lane == 0) {
#pragma unroll
        for (int e = 0; e < Em; e++) {
            lg[e] += br[e];
            logits_out[(size_t)t * Em + e] = lg[e];
        }
        float mx = lg[0];
#pragma unroll
        for (int e = 1; e < Em; e++) mx = fmaxf(mx, lg[e]);
        float p[Em]; float s = 0.f;
#pragma unroll
        for (int e = 0; e < Em; e++) { p[e] = expf(lg[e] - mx); s += p[e]; }
        float inv = 1.0f / s;
#pragma unroll
        for (int e = 0; e < Em; e++) p[e] *= inv;
        // top-2 with ties resolved to lower index (strict >), matching jax.lax.top_k
        int e0 = 0;
#pragma unroll
        for (int e = 1; e < Em; e++) if (p[e] > p[e0]) e0 = e;
        int e1 = (e0 == 0) ? 1 : 0;
#pragma unroll
        for (int e = 0; e < Em; e++) if (e != e0 && p[e] > p[e1]) e1 = e;
        float sum2 = p[e0] + p[e1];
        g_wt[2 * t + 0] = p[e0] / sum2;
        g_wt[2 * t + 1] = p[e1] / sum2;
        int pos0 = atomicAdd(&g_count[e0], 1);
        g_list[e0 * T_TOK + pos0] = 2 * t + 0;
        int pos1 = atomicAdd(&g_count[e1], 1);
        g_list[e1 * T_TOK + pos1] = 2 * t + 1;
    }
}

// Per (expert, 32-token tile): y = W2 @ gelu(W1 @ x), written unweighted to g_y slots.
extern __shared__ float smem[];
__global__ __launch_bounds__(256, 1)
void expert_kernel(const float* __restrict__ x,
                   const float* __restrict__ w1,
                   const float* __restrict__ w2) {
    const int e = blockIdx.y;
    const int cnt = g_count[e];
    const int base = blockIdx.x * TILE_T;
    if (base >= cnt) return;

    float* sX = smem;                    // [TILE_T][XS]
    float* sW = sX + TILE_T * XS;        // [128][WS]  (shared between W1 and W2 tiles)
    float* sH = sW + CH * WS;            // [TILE_T][HS]
    __shared__ int sEntry[TILE_T];
    __shared__ int sTok[TILE_T];

    const int tid = threadIdx.x;
    if (tid < TILE_T) {
        int idx = base + tid;
        int cl = idx < cnt ? idx : (cnt - 1);
        int entry = g_list[e * T_TOK + cl];
        sEntry[tid] = (idx < cnt) ? entry : -1;
        sTok[tid] = entry >> 1;
    }
    __syncthreads();

    // Gather X tile into smem (coalesced float4 per row)
    {
        const float4* xg = (const float4*)x;
        for (int i = tid; i < TILE_T * (Dm / 4); i += 256) {
            int row = i >> 7;        // Dm/4 = 128
            int c4  = i & 127;
            ((float4*)(sX + row * XS))[c4] = xg[(size_t)sTok[row] * (Dm / 4) + c4];
        }
    }

    const int tx = tid & 31;   // column group
    const int ty = tid >> 5;   // token group (rows ty, ty+8, ty+16, ty+24)

    float yacc[4][16];
#pragma unroll
    for (int r = 0; r < 4; r++)
#pragma unroll
        for (int m = 0; m < 16; m++) yacc[r][m] = 0.f;

    for (int hc = 0; hc < Hm; hc += CH) {
        // ---- fc1: h[32][128] = X[32][512] @ W1[e][hc:hc+128][:].T ----
        float hacc[4][4];
#pragma unroll
        for (int r = 0; r < 4; r++)
#pragma unroll
            for (int c = 0; c < 4; c++) hacc[r][c] = 0.f;

        for (int kt = 0; kt < Dm; kt += KT) {
            __syncthreads();  // prior sW users done
            const float4* wg = (const float4*)(w1 + ((size_t)e * Hm + hc) * Dm + kt);
            for (int i = tid; i < CH * (KT / 4); i += 256) {
                int row = i >> 5;  int c4 = i & 31;
                ((float4*)(sW + row * WS))[c4] = wg[(size_t)row * (Dm / 4) + c4];
            }
            __syncthreads();
#pragma unroll 2
            for (int k = 0; k < KT; k += 4) {
                float4 xvv[4], wvv[4];
#pragma unroll
                for (int r = 0; r < 4; r++)
                    xvv[r] = *(const float4*)&sX[(ty + 8 * r) * XS + kt + k];
#pragma unroll
                for (int c = 0; c < 4; c++)
                    wvv[c] = *(const float4*)&sW[(tx + 32 * c) * WS + k];
#pragma unroll
                for (int r = 0; r < 4; r++)
#pragma unroll
                    for (int c = 0; c < 4; c++) {
                        hacc[r][c] += xvv[r].x * wvv[c].x;
                        hacc[r][c] += xvv[r].y * wvv[c].y;
                        hacc[r][c] += xvv[r].z * wvv[c].z;
                        hacc[r][c] += xvv[r].w * wvv[c].w;
                    }
            }
        }

        // gelu (exact erf) -> sH
        __syncthreads();
#pragma unroll
        for (int r = 0; r < 4; r++)
#pragma unroll
            for (int c = 0; c < 4; c++) {
                float v = hacc[r][c];
                float g = 0.5f * v * (1.0f + erff(v * 0.70710678118654752f));
                sH[(ty + 8 * r) * HS + tx + 32 * c] = g;
            }
        __syncthreads();

        // ---- fc2 partial: y[32][512] += h[32][128] @ W2[e][:, hc:hc+128].T ----
        for (int dt = 0; dt < Dm; dt += 128) {
            const float4* wg2 = (const float4*)(w2 + ((size_t)e * Dm + dt) * Hm + hc);
            for (int i = tid; i < 128 * (CH / 4); i += 256) {
                int row = i >> 5;  int c4 = i & 31;
                ((float4*)(sW + row * WS))[c4] = wg2[(size_t)row * (Hm / 4) + c4];
            }
            __syncthreads();
            const int mbase = dt >> 5;
#pragma unroll 2
            for (int j = 0; j < CH; j += 4) {
                float4 hv[4], wvv[4];
#pragma unroll
                for (int r = 0; r < 4; r++)
                    hv[r] = *(const float4*)&sH[(ty + 8 * r) * HS + j];
#pragma unroll
                for (int c = 0; c < 4; c++)
                    wvv[c] = *(const float4*)&sW[(tx + 32 * c) * WS + j];
#pragma unroll
                for (int r = 0; r < 4; r++)
#pragma unroll
                    for (int c = 0; c < 4; c++) {
                        yacc[r][mbase + c] += hv[r].x * wvv[c].x + hv[r].y * wvv[c].y
                                            + hv[r].z * wvv[c].z + hv[r].w * wvv[c].w;
                    }
            }
            __syncthreads();  // done with this sW tile
        }
    }

    // Epilogue: unweighted y -> g_y slot per (token, slot) entry
#pragma unroll
    for (int r = 0; r < 4; r++) {
        int row = ty + 8 * r;
        int entry = sEntry[row];
        if (entry >= 0) {
            float* yp = g_y + (size_t)entry * Dm + tx;
#pragma unroll
            for (int m = 0; m < 16; m++) yp[32 * m] = yacc[r][m];
        }
    }
}

__global__ void combine_kernel(float* __restrict__ out) {
    int i = blockIdx.x * 256 + threadIdx.x;
    int t = i >> 9;        // Dm = 512
    int d = i & 511;
    float v = g_wt[2 * t + 0] * g_y[(size_t)(2 * t + 0) * Dm + d]
            + g_wt[2 * t + 1] * g_y[(size_t)(2 * t + 1) * Dm + d];
    out[i] = v;
}

extern "C" void kernel_launch(void* const* d_in, const int* in_sizes, int n_in,
                              void* d_out, int out_size) {
    const float* x  = (const float*)d_in[0];
    const float* wr = (const float*)d_in[1];
    const float* br = (const float*)d_in[2];
    const float* w1 = (const float*)d_in[3];
    const float* w2 = (const float*)d_in[4];
    float* out = (float*)d_out;
    float* logits = out + (size_t)T_TOK * Dm;  // [out (T*D) | router_logits (T*E)]

    size_t smem_bytes = (size_t)(TILE_T * XS + CH * WS + TILE_T * HS) * sizeof(float);
    cudaFuncSetAttribute(expert_kernel, cudaFuncAttributeMaxDynamicSharedMemorySize,
                         (int)smem_bytes);

    zero_counts_kernel<<<1, 32>>>();
    router_kernel<<<T_TOK / 8, 256>>>(x, wr, br, logits);
    dim3 grid(T_TOK / TILE_T, Em);
    expert_kernel<<<grid, 256, smem_bytes>>>(x, w1, w2);
    combine_kernel<<<(T_TOK * Dm) / 256, 256>>>(out);
}

// round 3
// speedup vs baseline: 2.3001x; 2.3001x over previous
#include <cuda_runtime.h>
#include <cuda_bf16.h>
#include <math.h>
#include <stdint.h>

#define T_TOK 2048
#define Dm    512
#define Hm    1024
#define Em    8
#define CAP   2048

// ---------------- scratch (static device globals) ----------------
__device__ int   g_count[Em];
__device__ int   g_list[Em * CAP];
__device__ float g_wt[2 * T_TOK];
__device__ float g_y[2 * T_TOK * Dm];

__device__ __align__(16) __nv_bfloat16 g_w1hi[Em * Hm * Dm];
__device__ __align__(16) __nv_bfloat16 g_w1lo[Em * Hm * Dm];
__device__ __align__(16) __nv_bfloat16 g_w2hi[Em * Dm * Hm];
__device__ __align__(16) __nv_bfloat16 g_w2lo[Em * Dm * Hm];
__device__ __align__(16) __nv_bfloat16 g_xhi[Em * CAP * Dm];
__device__ __align__(16) __nv_bfloat16 g_xlo[Em * CAP * Dm];
__device__ __align__(16) __nv_bfloat16 g_hhi[Em * CAP * Hm];
__device__ __align__(16) __nv_bfloat16 g_hlo[Em * CAP * Hm];

// ---------------- PTX helpers (all sm_80-era: safe at compute_103) ----------------
__device__ __forceinline__ uint32_t smem_u32(const void* p) {
    uint32_t a;
    asm("{ .reg .u64 t; cvta.to.shared.u64 t, %1; cvt.u32.u64 %0, t; }" : "=r"(a) : "l"(p));
    return a;
}
__device__ __forceinline__ void cp16(uint32_t dst, const void* src) {
    asm volatile("cp.async.cg.shared.global [%0], [%1], 16;" :: "r"(dst), "l"(src));
}
#define CP_COMMIT() asm volatile("cp.async.commit_group;" ::: "memory")
#define CP_WAIT(n)  asm volatile("cp.async.wait_group %0;" :: "n"(n) : "memory")

__device__ __forceinline__ uint32_t swz(uint32_t off) { return off ^ ((off >> 3) & 0x70); }

__device__ __forceinline__ void ldm_x4(uint32_t* r, uint32_t addr) {
    asm volatile("ldmatrix.sync.aligned.m8n8.x4.shared.b16 {%0,%1,%2,%3}, [%4];"
                 : "=r"(r[0]), "=r"(r[1]), "=r"(r[2]), "=r"(r[3]) : "r"(addr));
}
__device__ __forceinline__ void mma16816(float* c, const uint32_t* a, uint32_t b0, uint32_t b1) {
    asm volatile("mma.sync.aligned.m16n8k16.row.col.f32.bf16.bf16.f32 "
                 "{%0,%1,%2,%3}, {%4,%5,%6,%7}, {%8,%9}, {%0,%1,%2,%3};"
                 : "+f"(c[0]), "+f"(c[1]), "+f"(c[2]), "+f"(c[3])
                 : "r"(a[0]), "r"(a[1]), "r"(a[2]), "r"(a[3]), "r"(b0), "r"(b1));
}

// stage a 128-row x 64-col bf16 tile (128B rows) into SW128-swizzled smem via cp.async
__device__ __forceinline__ void stage_tile(uint32_t sbase, const __nv_bfloat16* src,
                                           int stride, int tid) {
    for (int q = tid; q < 1024; q += 256) {
        int r = q >> 3, c = q & 7;
        cp16(sbase + swz((uint32_t)(r * 128 + c * 16)), src + (size_t)r * stride + c * 8);
    }
}

// ---------------- small kernels ----------------
__global__ void zero_counts_kernel() {
    if (threadIdx.x < Em) g_count[threadIdx.x] = 0;
}

__device__ __forceinline__ void split8(const float* f, __nv_bfloat16* h, __nv_bfloat16* l) {
#pragma unroll
    for (int j = 0; j < 8; j++) {
        __nv_bfloat16 hh = __float2bfloat16_rn(f[j]);
        h[j] = hh;
        l[j] = __float2bfloat16_rn(f[j] - __bfloat162float(hh));
    }
}

__global__ void convertw1_kernel(const float* __restrict__ src) {
    int i = blockIdx.x * 256 + threadIdx.x;
    const float4* s = (const float4*)src + (size_t)i * 2;
    float4 a = s[0], b = s[1];
    float f[8] = {a.x, a.y, a.z, a.w, b.x, b.y, b.z, b.w};
    alignas(16) __nv_bfloat16 h[8], l[8];
    split8(f, h, l);
    *(uint4*)(g_w1hi + (size_t)i * 8) = *(uint4*)h;
    *(uint4*)(g_w1lo + (size_t)i * 8) = *(uint4*)l;
}
__global__ void convertw2_kernel(const float* __restrict__ src) {
    int i = blockIdx.x * 256 + threadIdx.x;
    const float4* s = (const float4*)src + (size_t)i * 2;
    float4 a = s[0], b = s[1];
    float f[8] = {a.x, a.y, a.z, a.w, b.x, b.y, b.z, b.w};
    alignas(16) __nv_bfloat16 h[8], l[8];
    split8(f, h, l);
    *(uint4*)(g_w2hi + (size_t)i * 8) = *(uint4*)h;
    *(uint4*)(g_w2lo + (size_t)i * 8) = *(uint4*)l;
}

__global__ void router_kernel(const float* __restrict__ x,
                              const float* __restrict__ wr,
                              const float* __restrict__ br,
                              float* __restrict__ logits_out) {
    int warp = threadIdx.x >> 5;
    int lane = threadIdx.x & 31;
    int t = blockIdx.x * 8 + warp;
    if (t >= T_TOK) return;

    const float4* xv4 = (const float4*)(x) + (size_t)t * (Dm / 4);
    float4 xv[4];
#pragma unroll
    for (int i = 0; i < 4; i++) xv[i] = xv4[i * 32 + lane];

    float lg[Em];
#pragma unroll
    for (int e = 0; e < Em; e++) {
        const float4* wv4 = (const float4*)(wr) + (size_t)e * (Dm / 4);
        float acc = 0.f;
#pragma unroll
        for (int i = 0; i < 4; i++) {
            float4 w = wv4[i * 32 + lane];
            acc += xv[i].x * w.x + xv[i].y * w.y + xv[i].z * w.z + xv[i].w * w.w;
        }
#pragma unroll
        for (int o = 16; o > 0; o >>= 1) acc += __shfl_down_sync(0xffffffffu, acc, o);
        lg[e] = acc;
    }

    if (lane == 0) {
#pragma unroll
        for (int e = 0; e < Em; e++) {
            lg[e] += br[e];
            logits_out[(size_t)t * Em + e] = lg[e];
        }
        float mx = lg[0];
#pragma unroll
        for (int e = 1; e < Em; e++) mx = fmaxf(mx, lg[e]);
        float p[Em]; float s = 0.f;
#pragma unroll
        for (int e = 0; e < Em; e++) { p[e] = expf(lg[e] - mx); s += p[e]; }
        float inv = 1.0f / s;
#pragma unroll
        for (int e = 0; e < Em; e++) p[e] *= inv;
        int e0 = 0;
#pragma unroll
        for (int e = 1; e < Em; e++) if (p[e] > p[e0]) e0 = e;
        int e1 = (e0 == 0) ? 1 : 0;
#pragma unroll
        for (int e = 0; e < Em; e++) if (e != e0 && p[e] > p[e1]) e1 = e;
        float sum2 = p[e0] + p[e1];
        g_wt[2 * t + 0] = p[e0] / sum2;
        g_wt[2 * t + 1] = p[e1] / sum2;
        int pos0 = atomicAdd(&g_count[e0], 1);
        g_list[e0 * CAP + pos0] = 2 * t + 0;
        int pos1 = atomicAdd(&g_count[e1], 1);
        g_list[e1 * CAP + pos1] = 2 * t + 1;
    }
}

__global__ void gather_kernel(const float* __restrict__ x) {
    int gw = (blockIdx.x * 256 + threadIdx.x) >> 5;
    int lane = threadIdx.x & 31;
    int e = gw >> 11;
    int pos = gw & (CAP - 1);
    if (e >= Em || pos >= g_count[e]) return;
    int tok = g_list[e * CAP + pos] >> 1;
    const float4* src = (const float4*)(x + (size_t)tok * Dm);
    __nv_bfloat16* dh = g_xhi + ((size_t)e * CAP + pos) * Dm;
    __nv_bfloat16* dl = g_xlo + ((size_t)e * CAP + pos) * Dm;
#pragma unroll
    for (int i = 0; i < 4; i++) {
        float4 v = src[i * 32 + lane];
        float f[4] = {v.x, v.y, v.z, v.w};
        alignas(8) __nv_bfloat16 h[4], l[4];
#pragma unroll
        for (int j = 0; j < 4; j++) {
            __nv_bfloat16 hh = __float2bfloat16_rn(f[j]);
            h[j] = hh;
            l[j] = __float2bfloat16_rn(f[j] - __bfloat162float(hh));
        }
        int eo = (i * 32 + lane) * 4;
        *(uint2*)(dh + eo) = *(uint2*)h;
        *(uint2*)(dl + eo) = *(uint2*)l;
    }
}

// ---------------- warp-MMA GEMM mainloop (shared pattern) ----------------
// CTA 128x128, 8 warps (2 M x 4 N), warp tile 64x32, m16n8k16 bf16, fp32 accum.
// smem: 2 stages x (A 16KB + B 16KB) = 64KB, SW128 swizzle, cp.async double buffer.

extern __shared__ char smx[];

#define GEMM_MAINLOOP(NT, SEG_SHIFT, SEG_MASK, STRIDE)                               \
    uint32_t smb = smem_u32(smx);                                                     \
    stage_tile(smb,         Aseg[0] + aoff, STRIDE, tid);                             \
    stage_tile(smb + 16384, Bseg[0] + boff, STRIDE, tid);                             \
    CP_COMMIT();                                                                      \
    float acc[4][4][4];                                                               \
    _Pragma("unroll") for (int a1 = 0; a1 < 4; a1++)                                  \
    _Pragma("unroll") for (int a2 = 0; a2 < 4; a2++)                                  \
    _Pragma("unroll") for (int a3 = 0; a3 < 4; a3++) acc[a1][a2][a3] = 0.f;           \
    const int lr = lane & 15, lc = lane >> 4;                                         \
    for (int i = 0; i < NT; i++) {                                                    \
        const int buf = i & 1;                                                        \
        if (i + 1 < NT) {                                                             \
            const int nx = i + 1;                                                     \
            const int seg = nx >> SEG_SHIFT, kt = nx & SEG_MASK;                      \
            uint32_t sb2 = smb + ((nx) & 1) * 32768;                                  \
            stage_tile(sb2,         Aseg[seg] + aoff + kt * 64, STRIDE, tid);         \
            stage_tile(sb2 + 16384, Bseg[seg] + boff + kt * 64, STRIDE, tid);         \
            CP_COMMIT();                                                              \
            CP_WAIT(1);                                                               \
        } else {                                                                      \
            CP_WAIT(0);                                                               \
        }                                                                             \
        __syncthreads();                                                              \
        uint32_t sa = smb + buf * 32768, sbb = sa + 16384;                            \
        _Pragma("unroll")                                                             \
        for (int kk = 0; kk < 64; kk += 16) {                                         \
            uint32_t af[4][4];                                                        \
            _Pragma("unroll")                                                         \
            for (int mi = 0; mi < 4; mi++) {                                          \
                uint32_t off = (uint32_t)((warpM * 64 + mi * 16 + lr) * 128           \
                                          + (kk / 8 + lc) * 16);                      \
                ldm_x4(af[mi], sa + swz(off));                                        \
            }                                                                         \
            uint32_t bfr[2][4];                                                       \
            _Pragma("unroll")                                                         \
            for (int nj = 0; nj < 2; nj++) {                                          \
                uint32_t off = (uint32_t)((warpN * 32 + nj * 16 + lr) * 128           \
                                          + (kk / 8 + lc) * 16);                      \
                ldm_x4(bfr[nj], sbb + swz(off));                                      \
            }                                                                         \
            _Pragma("unroll")                                                         \
            for (int mi = 0; mi < 4; mi++)                                            \
                _Pragma("unroll")                                                     \
                for (int ni = 0; ni < 4; ni++) {                                      \
                    const int nj = ni >> 1, sub = ni & 1;                             \
                    mma16816(acc[mi][ni], af[mi], bfr[nj][sub], bfr[nj][sub + 2]);    \
                }                                                                     \
        }                                                                             \
        __syncthreads();                                                              \
    }

// ---------------- fc1: h = gelu(X @ W1^T) ----------------
__global__ __launch_bounds__(256, 1) void fc1_kernel() {
    const int e = blockIdx.z;
    const int cnt = g_count[e];
    const int rowbase = blockIdx.y * 128;
    if (rowbase >= cnt) return;
    const int nbase = blockIdx.x * 128;

    const int tid = threadIdx.x;
    const int wid = tid >> 5, lane = tid & 31;
    const int warpM = wid >> 2, warpN = wid & 3;

    const __nv_bfloat16* Aseg[3] = {g_xhi, g_xhi, g_xlo};
    const __nv_bfloat16* Bseg[3] = {g_w1hi, g_w1lo, g_w1hi};
    const size_t aoff = ((size_t)e * CAP + rowbase) * Dm;
    const size_t boff = ((size_t)e * Hm + nbase) * Dm;

    GEMM_MAINLOOP(24, 3, 7, Dm)   // 3 segs x 8 ktiles of 64 (K=512)

    // epilogue: gelu + bf16 split
    const int r0 = lane >> 2, c0 = (lane & 3) * 2;
#pragma unroll
    for (int mi = 0; mi < 4; mi++) {
#pragma unroll
        for (int half = 0; half < 2; half++) {
            int row = rowbase + warpM * 64 + mi * 16 + r0 + half * 8;
            size_t rg = ((size_t)e * CAP + row) * Hm + nbase + warpN * 32 + c0;
#pragma unroll
            for (int ni = 0; ni < 4; ni++) {
                float v0 = acc[mi][ni][half * 2 + 0];
                float v1 = acc[mi][ni][half * 2 + 1];
                float gg0 = 0.5f * v0 * (1.0f + erff(v0 * 0.70710678118654752f));
                float gg1 = 0.5f * v1 * (1.0f + erff(v1 * 0.70710678118654752f));
                __nv_bfloat16 h0 = __float2bfloat16_rn(gg0);
                __nv_bfloat16 h1 = __float2bfloat16_rn(gg1);
                __nv_bfloat16 l0 = __float2bfloat16_rn(gg0 - __bfloat162float(h0));
                __nv_bfloat16 l1 = __float2bfloat16_rn(gg1 - __bfloat162float(h1));
                uint32_t hp = (uint32_t)*(uint16_t*)&h0 | ((uint32_t)*(uint16_t*)&h1 << 16);
                uint32_t lp = (uint32_t)*(uint16_t*)&l0 | ((uint32_t)*(uint16_t*)&l1 << 16);
                *(uint32_t*)(g_hhi + rg + ni * 8) = hp;
                *(uint32_t*)(g_hlo + rg + ni * 8) = lp;
            }
        }
    }
}

// ---------------- fc2: y = H @ W2^T (masked scatter to g_y) ----------------
__global__ __launch_bounds__(256, 1) void fc2_kernel() {
    const int e = blockIdx.z;
    const int cnt = g_count[e];
    const int rowbase = blockIdx.y * 128;
    if (rowbase >= cnt) return;
    const int nbase = blockIdx.x * 128;

    const int tid = threadIdx.x;
    const int wid = tid >> 5, lane = tid & 31;
    const int warpM = wid >> 2, warpN = wid & 3;

    const __nv_bfloat16* Aseg[3] = {g_hhi, g_hhi, g_hlo};
    const __nv_bfloat16* Bseg[3] = {g_w2hi, g_w2lo, g_w2hi};
    const size_t aoff = ((size_t)e * CAP + rowbase) * Hm;
    const size_t boff = ((size_t)e * Dm + nbase) * Hm;

    GEMM_MAINLOOP(48, 4, 15, Hm)  // 3 segs x 16 ktiles of 64 (K=1024)

    const int r0 = lane >> 2, c0 = (lane & 3) * 2;
#pragma unroll
    for (int mi = 0; mi < 4; mi++) {
#pragma unroll
        for (int half = 0; half < 2; half++) {
            int pos = rowbase + warpM * 64 + mi * 16 + r0 + half * 8;
            if (pos >= cnt) continue;
            int entry = g_list[e * CAP + pos];
            float* yp = g_y + (size_t)entry * Dm + nbase + warpN * 32 + c0;
#pragma unroll
            for (int ni = 0; ni < 4; ni++) {
                float2 v = make_float2(acc[mi][ni][half * 2 + 0],
                                       acc[mi][ni][half * 2 + 1]);
                *(float2*)(yp + ni * 8) = v;
            }
        }
    }
}

__global__ void combine_kernel(float* __restrict__ out) {
    int i = blockIdx.x * 256 + threadIdx.x;
    int t = i >> 7, c = i & 127;
    float w0 = g_wt[2 * t + 0], w1v = g_wt[2 * t + 1];
    float4 a = ((const float4*)(g_y + (size_t)(2 * t + 0) * Dm))[c];
    float4 b = ((const float4*)(g_y + (size_t)(2 * t + 1) * Dm))[c];
    float4 o;
    o.x = w0 * a.x + w1v * b.x;
    o.y = w0 * a.y + w1v * b.y;
    o.z = w0 * a.z + w1v * b.z;
    o.w = w0 * a.w + w1v * b.w;
    ((float4*)out)[i] = o;
}

// ---------------- launch ----------------
extern "C" void kernel_launch(void* const* d_in, const int* in_sizes, int n_in,
                              void* d_out, int out_size) {
    const float* x  = (const float*)d_in[0];
    const float* wr = (const float*)d_in[1];
    const float* br = (const float*)d_in[2];
    const float* w1 = (const float*)d_in[3];
    const float* w2 = (const float*)d_in[4];
    float* out = (float*)d_out;
    float* logits = out + (size_t)T_TOK * Dm;

    static int attr_done = 0;
    if (!attr_done) {
        cudaFuncSetAttribute(fc1_kernel, cudaFuncAttributeMaxDynamicSharedMemorySize, 65536);
        cudaFuncSetAttribute(fc2_kernel, cudaFuncAttributeMaxDynamicSharedMemorySize, 65536);
        attr_done = 1;
    }

    zero_counts_kernel<<<1, 32>>>();
    {
        int n8 = (Em * Hm * Dm) / 8;
        convertw1_kernel<<<n8 / 256, 256>>>(w1);
        convertw2_kernel<<<n8 / 256, 256>>>(w2);
    }
    router_kernel<<<T_TOK / 8, 256>>>(x, wr, br, logits);
    gather_kernel<<<(Em * CAP * 32) / 256, 256>>>(x);

    dim3 g1(Hm / 128, CAP / 128, Em);   // (8, 16, 8)
    fc1_kernel<<<g1, 256, 65536>>>();
    dim3 g2(Dm / 128, CAP / 128, Em);   // (4, 16, 8)
    fc2_kernel<<<g2, 256, 65536>>>();
    combine_kernel<<<(T_TOK * 128) / 256, 256>>>(out);
}

// round 4
// speedup vs baseline: 2.3291x; 1.0126x over previous
#include <cuda_runtime.h>
#include <cuda_bf16.h>
#include <math.h>
#include <stdint.h>

#define T_TOK 2048
#define Dm    512
#define Hm    1024
#define Em    8
#define CAP   2048

// ---------------- scratch (static device globals) ----------------
__device__ int   g_count[Em];
__device__ int   g_list[Em * CAP];
__device__ float g_wt[2 * T_TOK];

__device__ __align__(16) __nv_bfloat16 g_w1hi[Em * Hm * Dm];
__device__ __align__(16) __nv_bfloat16 g_w1lo[Em * Hm * Dm];
__device__ __align__(16) __nv_bfloat16 g_w2hi[Em * Dm * Hm];
__device__ __align__(16) __nv_bfloat16 g_w2lo[Em * Dm * Hm];
__device__ __align__(16) __nv_bfloat16 g_xhi[Em * CAP * Dm];
__device__ __align__(16) __nv_bfloat16 g_xlo[Em * CAP * Dm];
__device__ __align__(16) __nv_bfloat16 g_hhi[Em * CAP * Hm];
__device__ __align__(16) __nv_bfloat16 g_hlo[Em * CAP * Hm];

// ---------------- PTX helpers ----------------
__device__ __forceinline__ uint32_t smem_u32(const void* p) {
    uint32_t a;
    asm("{ .reg .u64 t; cvta.to.shared.u64 t, %1; cvt.u32.u64 %0, t; }" : "=r"(a) : "l"(p));
    return a;
}
__device__ __forceinline__ void cp16(uint32_t dst, const void* src) {
    asm volatile("cp.async.cg.shared.global [%0], [%1], 16;" :: "r"(dst), "l"(src));
}
#define CP_COMMIT() asm volatile("cp.async.commit_group;" ::: "memory")
#define CP_WAIT(n)  asm volatile("cp.async.wait_group %0;" :: "n"(n) : "memory")

__device__ __forceinline__ uint32_t swz(uint32_t off) { return off ^ ((off >> 3) & 0x70); }

__device__ __forceinline__ void ldm_x4(uint32_t* r, uint32_t addr) {
    asm volatile("ldmatrix.sync.aligned.m8n8.x4.shared.b16 {%0,%1,%2,%3}, [%4];"
                 : "=r"(r[0]), "=r"(r[1]), "=r"(r[2]), "=r"(r[3]) : "r"(addr));
}
__device__ __forceinline__ void mma16816(float* c, const uint32_t* a, uint32_t b0, uint32_t b1) {
    asm volatile("mma.sync.aligned.m16n8k16.row.col.f32.bf16.bf16.f32 "
                 "{%0,%1,%2,%3}, {%4,%5,%6,%7}, {%8,%9}, {%0,%1,%2,%3};"
                 : "+f"(c[0]), "+f"(c[1]), "+f"(c[2]), "+f"(c[3])
                 : "r"(a[0]), "r"(a[1]), "r"(a[2]), "r"(a[3]), "r"(b0), "r"(b1));
}

__device__ __forceinline__ void stage_tile(uint32_t sbase, const __nv_bfloat16* src,
                                           int stride, int tid) {
    for (int q = tid; q < 1024; q += 256) {
        int r = q >> 3, c = q & 7;
        cp16(sbase + swz((uint32_t)(r * 128 + c * 16)), src + (size_t)r * stride + c * 8);
    }
}

// ---------------- zero: out buffer + counts ----------------
__global__ void zero_kernel(float* __restrict__ out) {
    int i = blockIdx.x * 256 + threadIdx.x;
    ((float4*)out)[i] = make_float4(0.f, 0.f, 0.f, 0.f);   // first T*D floats
    if (blockIdx.x == 0 && threadIdx.x < Em) g_count[threadIdx.x] = 0;
}

__device__ __forceinline__ void split8(const float* f, __nv_bfloat16* h, __nv_bfloat16* l) {
#pragma unroll
    for (int j = 0; j < 8; j++) {
        __nv_bfloat16 hh = __float2bfloat16_rn(f[j]);
        h[j] = hh;
        l[j] = __float2bfloat16_rn(f[j] - __bfloat162float(hh));
    }
}

__global__ void convertw1_kernel(const float* __restrict__ src) {
    int i = blockIdx.x * 256 + threadIdx.x;
    const float4* s = (const float4*)src + (size_t)i * 2;
    float4 a = s[0], b = s[1];
    float f[8] = {a.x, a.y, a.z, a.w, b.x, b.y, b.z, b.w};
    alignas(16) __nv_bfloat16 h[8], l[8];
    split8(f, h, l);
    *(uint4*)(g_w1hi + (size_t)i * 8) = *(uint4*)h;
    *(uint4*)(g_w1lo + (size_t)i * 8) = *(uint4*)l;
}
__global__ void convertw2_kernel(const float* __restrict__ src) {
    int i = blockIdx.x * 256 + threadIdx.x;
    const float4* s = (const float4*)src + (size_t)i * 2;
    float4 a = s[0], b = s[1];
    float f[8] = {a.x, a.y, a.z, a.w, b.x, b.y, b.z, b.w};
    alignas(16) __nv_bfloat16 h[8], l[8];
    split8(f, h, l);
    *(uint4*)(g_w2hi + (size_t)i * 8) = *(uint4*)h;
    *(uint4*)(g_w2lo + (size_t)i * 8) = *(uint4*)l;
}

// ---------------- router + fused gather ----------------
__global__ __launch_bounds__(256) void router_kernel(const float* __restrict__ x,
                                                     const float* __restrict__ wr,
                                                     const float* __restrict__ br,
                                                     float* __restrict__ logits_out) {
    const int warp = threadIdx.x >> 5;
    const int lane = threadIdx.x & 31;
    const int t = blockIdx.x * 8 + warp;

    const float4* xv4 = (const float4*)(x) + (size_t)t * (Dm / 4);
    float4 xv[4];
#pragma unroll
    for (int i = 0; i < 4; i++) xv[i] = xv4[i * 32 + lane];

    float acc[Em];
#pragma unroll
    for (int e = 0; e < Em; e++) {
        const float4* wv4 = (const float4*)(wr) + (size_t)e * (Dm / 4);
        float a = 0.f;
#pragma unroll
        for (int i = 0; i < 4; i++) {
            float4 w = wv4[i * 32 + lane];
            a += xv[i].x * w.x + xv[i].y * w.y + xv[i].z * w.z + xv[i].w * w.w;
        }
        acc[e] = a;
    }
    // butterfly all-reduce: 8 independent chains, 5 rounds
#pragma unroll
    for (int off = 16; off > 0; off >>= 1)
#pragma unroll
        for (int e = 0; e < Em; e++)
            acc[e] += __shfl_xor_sync(0xffffffffu, acc[e], off);
#pragma unroll
    for (int e = 0; e < Em; e++) acc[e] += br[e];

    int pack0 = 0, pack1 = 0;
    if (lane == 0) {
        *(float4*)(logits_out + (size_t)t * Em)     = make_float4(acc[0], acc[1], acc[2], acc[3]);
        *(float4*)(logits_out + (size_t)t * Em + 4) = make_float4(acc[4], acc[5], acc[6], acc[7]);
        float mx = acc[0];
#pragma unroll
        for (int e = 1; e < Em; e++) mx = fmaxf(mx, acc[e]);
        float p[Em]; float s = 0.f;
#pragma unroll
        for (int e = 0; e < Em; e++) { p[e] = expf(acc[e] - mx); s += p[e]; }
        float inv = 1.0f / s;
#pragma unroll
        for (int e = 0; e < Em; e++) p[e] *= inv;
        int e0 = 0;
#pragma unroll
        for (int e = 1; e < Em; e++) if (p[e] > p[e0]) e0 = e;
        int e1 = (e0 == 0) ? 1 : 0;
#pragma unroll
        for (int e = 0; e < Em; e++) if (e != e0 && p[e] > p[e1]) e1 = e;
        float sum2 = p[e0] + p[e1];
        g_wt[2 * t + 0] = p[e0] / sum2;
        g_wt[2 * t + 1] = p[e1] / sum2;
        int pos0 = atomicAdd(&g_count[e0], 1);
        g_list[e0 * CAP + pos0] = 2 * t + 0;
        int pos1 = atomicAdd(&g_count[e1], 1);
        g_list[e1 * CAP + pos1] = 2 * t + 1;
        pack0 = (e0 << 16) | pos0;
        pack1 = (e1 << 16) | pos1;
    }
    pack0 = __shfl_sync(0xffffffffu, pack0, 0);
    pack1 = __shfl_sync(0xffffffffu, pack1, 0);
    const int e0 = pack0 >> 16, pos0 = pack0 & 0xffff;
    const int e1 = pack1 >> 16, pos1 = pack1 & 0xffff;

    __nv_bfloat16* dh0 = g_xhi + ((size_t)e0 * CAP + pos0) * Dm;
    __nv_bfloat16* dl0 = g_xlo + ((size_t)e0 * CAP + pos0) * Dm;
    __nv_bfloat16* dh1 = g_xhi + ((size_t)e1 * CAP + pos1) * Dm;
    __nv_bfloat16* dl1 = g_xlo + ((size_t)e1 * CAP + pos1) * Dm;
#pragma unroll
    for (int i = 0; i < 4; i++) {
        float f[4] = {xv[i].x, xv[i].y, xv[i].z, xv[i].w};
        alignas(8) __nv_bfloat16 h[4], l[4];
#pragma unroll
        for (int j = 0; j < 4; j++) {
            __nv_bfloat16 hh = __float2bfloat16_rn(f[j]);
            h[j] = hh;
            l[j] = __float2bfloat16_rn(f[j] - __bfloat162float(hh));
        }
        int eo = (i * 32 + lane) * 4;
        *(uint2*)(dh0 + eo) = *(uint2*)h;
        *(uint2*)(dl0 + eo) = *(uint2*)l;
        *(uint2*)(dh1 + eo) = *(uint2*)h;
        *(uint2*)(dl1 + eo) = *(uint2*)l;
    }
}

// ---------------- warp-MMA GEMM mainloop: 3-stage, 1 sync/iter ----------------
extern __shared__ char smx[];

#define STAGE_J(j, bufi)                                                              \
    do {                                                                              \
        const int seg_ = (j) >> SEG_SHIFT, kt_ = (j) & SEG_MASK;                      \
        uint32_t sb2_ = smb + (bufi) * 32768;                                         \
        stage_tile(sb2_,         Aseg[seg_] + aoff + kt_ * 64, STRIDE, tid);          \
        stage_tile(sb2_ + 16384, Bseg[seg_] + boff + kt_ * 64, STRIDE, tid);          \
        CP_COMMIT();                                                                  \
    } while (0)

#define GEMM_MAINLOOP(NT, SEG_SHIFT_V, SEG_MASK_V, STRIDE_V)                          \
    enum { SEG_SHIFT = SEG_SHIFT_V, SEG_MASK = SEG_MASK_V, STRIDE = STRIDE_V };       \
    uint32_t smb = smem_u32(smx);                                                     \
    STAGE_J(0, 0);                                                                    \
    STAGE_J(1, 1);                                                                    \
    float acc[4][4][4];                                                               \
    _Pragma("unroll") for (int a1 = 0; a1 < 4; a1++)                                  \
    _Pragma("unroll") for (int a2 = 0; a2 < 4; a2++)                                  \
    _Pragma("unroll") for (int a3 = 0; a3 < 4; a3++) acc[a1][a2][a3] = 0.f;           \
    const int lr = lane & 15, lc = lane >> 4;                                         \
    int bc = 0, bs = 2;                                                               \
    for (int i = 0; i < NT; i++) {                                                    \
        if (i < NT - 1) CP_WAIT(1); else CP_WAIT(0);                                  \
        __syncthreads();                                                              \
        if (i + 2 < NT) { STAGE_J(i + 2, bs); bs = (bs == 2) ? 0 : bs + 1; }          \
        uint32_t sa = smb + bc * 32768, sbb = sa + 16384;                             \
        bc = (bc == 2) ? 0 : bc + 1;                                                  \
        _Pragma("unroll")                                                             \
        for (int kk = 0; kk < 64; kk += 16) {                                         \
            uint32_t af[4][4];                                                        \
            _Pragma("unroll")                                                         \
            for (int mi = 0; mi < 4; mi++) {                                          \
                uint32_t off = (uint32_t)((warpM * 64 + mi * 16 + lr) * 128           \
                                          + (kk / 8 + lc) * 16);                      \
                ldm_x4(af[mi], sa + swz(off));                                        \
            }                                                                         \
            uint32_t bfr[2][4];                                                       \
            _Pragma("unroll")                                                         \
            for (int nj = 0; nj < 2; nj++) {                                          \
                uint32_t off = (uint32_t)((warpN * 32 + nj * 16 + lr) * 128           \
                                          + (kk / 8 + lc) * 16);                      \
                ldm_x4(bfr[nj], sbb + swz(off));                                      \
            }                                                                         \
            _Pragma("unroll")                                                         \
            for (int mi = 0; mi < 4; mi++)                                            \
                _Pragma("unroll")                                                     \
                for (int ni = 0; ni < 4; ni++) {                                      \
                    const int nj = ni >> 1, sub = ni & 1;                             \
                    mma16816(acc[mi][ni], af[mi], bfr[nj][sub], bfr[nj][sub + 2]);    \
                }                                                                     \
        }                                                                             \
    }

// ---------------- fc1: h = gelu(X @ W1^T) ----------------
__global__ __launch_bounds__(256, 1) void fc1_kernel() {
    const int e = blockIdx.z;
    const int cnt = g_count[e];
    const int rowbase = blockIdx.y * 128;
    if (rowbase >= cnt) return;
    const int nbase = blockIdx.x * 128;

    const int tid = threadIdx.x;
    const int wid = tid >> 5, lane = tid & 31;
    const int warpM = wid >> 2, warpN = wid & 3;

    const __nv_bfloat16* Aseg[3] = {g_xhi, g_xhi, g_xlo};
    const __nv_bfloat16* Bseg[3] = {g_w1hi, g_w1lo, g_w1hi};
    const size_t aoff = ((size_t)e * CAP + rowbase) * Dm;
    const size_t boff = ((size_t)e * Hm + nbase) * Dm;

    GEMM_MAINLOOP(24, 3, 7, Dm)

    const int r0 = lane >> 2, c0 = (lane & 3) * 2;
#pragma unroll
    for (int mi = 0; mi < 4; mi++) {
#pragma unroll
        for (int half = 0; half < 2; half++) {
            int row = rowbase + warpM * 64 + mi * 16 + r0 + half * 8;
            size_t rg = ((size_t)e * CAP + row) * Hm + nbase + warpN * 32 + c0;
#pragma unroll
            for (int ni = 0; ni < 4; ni++) {
                float v0 = acc[mi][ni][half * 2 + 0];
                float v1 = acc[mi][ni][half * 2 + 1];
                float gg0 = 0.5f * v0 * (1.0f + erff(v0 * 0.70710678118654752f));
                float gg1 = 0.5f * v1 * (1.0f + erff(v1 * 0.70710678118654752f));
                __nv_bfloat16 h0 = __float2bfloat16_rn(gg0);
                __nv_bfloat16 h1 = __float2bfloat16_rn(gg1);
                __nv_bfloat16 l0 = __float2bfloat16_rn(gg0 - __bfloat162float(h0));
                __nv_bfloat16 l1 = __float2bfloat16_rn(gg1 - __bfloat162float(h1));
                uint32_t hp = (uint32_t)*(uint16_t*)&h0 | ((uint32_t)*(uint16_t*)&h1 << 16);
                uint32_t lp = (uint32_t)*(uint16_t*)&l0 | ((uint32_t)*(uint16_t*)&l1 << 16);
                *(uint32_t*)(g_hhi + rg + ni * 8) = hp;
                *(uint32_t*)(g_hlo + rg + ni * 8) = lp;
            }
        }
    }
}

// ---------------- fc2: out[tok] += w * (H @ W2^T)  (atomic combine) ----------------
__global__ __launch_bounds__(256, 1) void fc2_kernel(float* __restrict__ out) {
    const int e = blockIdx.z;
    const int cnt = g_count[e];
    const int rowbase = blockIdx.y * 128;
    if (rowbase >= cnt) return;
    const int nbase = blockIdx.x * 128;

    const int tid = threadIdx.x;
    const int wid = tid >> 5, lane = tid & 31;
    const int warpM = wid >> 2, warpN = wid & 3;

    const __nv_bfloat16* Aseg[3] = {g_hhi, g_hhi, g_hlo};
    const __nv_bfloat16* Bseg[3] = {g_w2hi, g_w2lo, g_w2hi};
    const size_t aoff = ((size_t)e * CAP + rowbase) * Hm;
    const size_t boff = ((size_t)e * Dm + nbase) * Hm;

    GEMM_MAINLOOP(48, 4, 15, Hm)

    const int r0 = lane >> 2, c0 = (lane & 3) * 2;
#pragma unroll
    for (int mi = 0; mi < 4; mi++) {
#pragma unroll
        for (int half = 0; half < 2; half++) {
            int pos = rowbase + warpM * 64 + mi * 16 + r0 + half * 8;
            if (pos >= cnt) continue;
            int entry = g_list[e * CAP + pos];
            float w = g_wt[entry];
            int tok = entry >> 1;
            float* op = out + (size_t)tok * Dm + nbase + warpN * 32 + c0;
#pragma unroll
            for (int ni = 0; ni < 4; ni++) {
                atomicAdd(op + ni * 8,     w * acc[mi][ni][half * 2 + 0]);
                atomicAdd(op + ni * 8 + 1, w * acc[mi][ni][half * 2 + 1]);
            }
        }
    }
}

// ---------------- launch ----------------
extern "C" void kernel_launch(void* const* d_in, const int* in_sizes, int n_in,
                              void* d_out, int out_size) {
    const float* x  = (const float*)d_in[0];
    const float* wr = (const float*)d_in[1];
    const float* br = (const float*)d_in[2];
    const float* w1 = (const float*)d_in[3];
    const float* w2 = (const float*)d_in[4];
    float* out = (float*)d_out;
    float* logits = out + (size_t)T_TOK * Dm;

    static int attr_done = 0;
    if (!attr_done) {
        cudaFuncSetAttribute(fc1_kernel, cudaFuncAttributeMaxDynamicSharedMemorySize, 98304);
        cudaFuncSetAttribute(fc2_kernel, cudaFuncAttributeMaxDynamicSharedMemorySize, 98304);
        attr_done = 1;
    }

    zero_kernel<<<(T_TOK * Dm / 4) / 256, 256>>>(out);      // 1
    int n8 = (Em * Hm * Dm) / 8;
    convertw1_kernel<<<n8 / 256, 256>>>(w1);                 // 2
    convertw2_kernel<<<n8 / 256, 256>>>(w2);                 // 3
    router_kernel<<<T_TOK / 8, 256>>>(x, wr, br, logits);    // 4
    dim3 g1(Hm / 128, CAP / 128, Em);
    fc1_kernel<<<g1, 256, 98304>>>();                        // 5
    dim3 g2(Dm / 128, CAP / 128, Em);
    fc2_kernel<<<g2, 256, 98304>>>(out);                     // 6
}